// round 8
// baseline (speedup 1.0000x reference)
#include <cuda_runtime.h>
#include <cstdint>

#define BB 32
#define NN 2048
#define CIN 64
#define COUTC 128
#define ADJ_EPS 1e-6f
#define BN_EPS 1e-5f

// smem geometry (floats)
#define SA_STRIDE 36          // 36 % 32 == 4 -> conflict-free a-frag LDS
#define SB_STRIDE 136         // 136 % 32 == 8 -> conflict-free b-frag LDS
#define SA_BYTES (64 * SA_STRIDE * 4)    // 9216
#define SB_BYTES (32 * SB_STRIDE * 4)    // 17408
#define STAGE_BYTES (SA_BYTES + SB_BYTES)  // 26624
#define NSTAGE 3
#define SMEM_BYTES (NSTAGE * STAGE_BYTES)  // 79872

// ---------------- scratch (device globals; no allocations allowed) ----------
__device__ float g_invS[BB * NN];
__device__ float g_xsT[(size_t)BB * 64 * NN];      // xsT[b][c][n] = tf32(x[b][n][c]*invS)
__device__ float g_h[(size_t)BB * NN * COUTC];     // pre-BN activations [b][m][o]
__device__ float g_stats[2 * COUTC];

__device__ __forceinline__ uint32_t smem_u32(const void* p) {
    uint32_t a;
    asm("{ .reg .u64 t; cvta.to.shared.u64 t, %1; cvt.u32.u64 %0, t; }" : "=r"(a) : "l"(p));
    return a;
}
__device__ __forceinline__ void cp16(uint32_t dst, const void* src) {
    asm volatile("cp.async.cg.shared.global [%0], [%1], 16;" :: "r"(dst), "l"(src));
}

// ---------------------------------------------------------------------------
// K1: row sums of A (one warp per row); block 0 zeroes g_stats.
// ---------------------------------------------------------------------------
__global__ void k_rowsum(const float* __restrict__ A) {
    if (blockIdx.x == 0 && threadIdx.x < 2 * COUTC) g_stats[threadIdx.x] = 0.f;
    int row = blockIdx.x * (blockDim.x >> 5) + (threadIdx.x >> 5);
    int lane = threadIdx.x & 31;
    if (row >= BB * NN) return;
    const float4* Ar = reinterpret_cast<const float4*>(A + (size_t)row * NN);
    float s = 0.f;
#pragma unroll 4
    for (int i = lane; i < NN / 4; i += 32) {
        float4 v = Ar[i];
        s += v.x + v.y + v.z + v.w;
    }
#pragma unroll
    for (int o = 16; o; o >>= 1) s += __shfl_xor_sync(0xFFFFFFFFu, s, o);
    if (lane == 0) g_invS[row] = 1.0f / (s + ADJ_EPS);
}

// ---------------------------------------------------------------------------
// K1b: xsT[b][c][n] = tf32(x[b][n][c] * invS[b][n]), transposed via smem
// ---------------------------------------------------------------------------
__global__ void __launch_bounds__(256) k_prep(const float* __restrict__ x) {
    __shared__ float sx[64 * 65];
    __shared__ float sinv[64];
    const int b = blockIdx.y, n0 = blockIdx.x * 64, tid = threadIdx.x;
    if (tid < 64) sinv[tid] = g_invS[b * NN + n0 + tid];
#pragma unroll
    for (int l = 0; l < 4; l++) {
        int i = tid + 256 * l;
        int n = i >> 4, c4 = i & 15;
        float4 v = *reinterpret_cast<const float4*>(x + ((size_t)b * NN + n0 + n) * 64 + c4 * 4);
        sx[n * 65 + c4 * 4 + 0] = v.x;
        sx[n * 65 + c4 * 4 + 1] = v.y;
        sx[n * 65 + c4 * 4 + 2] = v.z;
        sx[n * 65 + c4 * 4 + 3] = v.w;
    }
    __syncthreads();
#pragma unroll
    for (int l = 0; l < 16; l++) {
        int i = tid + 256 * l;
        int c = i >> 6, n = i & 63;
        float v = sx[n * 65 + c] * sinv[n];
        uint32_t u;
        asm("cvt.rna.tf32.f32 %0, %1;" : "=r"(u) : "f"(v));
        g_xsT[((size_t)b * 64 + c) * NN + n0 + n] = __uint_as_float(u);
    }
}

// ---------------------------------------------------------------------------
// K2: warp-level tf32 mma.sync GEMM + fused 1x1 conv + BN stats.
// Per CTA: D[c(64), m(128)] = sum_n xsT[c][n] * A[n][m0+m], K = 2048.
// 512 threads (16 warps: wc = w&1 c-half, wm = w>>1 m-group of 16).
// 3-stage cp.async ring, 1 sync/chunk, copies issued before compute.
// ---------------------------------------------------------------------------
__global__ void __launch_bounds__(512, 2) k_gemm(const float* __restrict__ A,
                                                 const float* __restrict__ Wm,
                                                 const float* __restrict__ bias) {
    extern __shared__ float sm[];
    __shared__ float s_sum[COUTC], s_sq[COUTC];

    const uint32_t smb = smem_u32(sm);
    const int tid = threadIdx.x;
    const int w = tid >> 5, lane = tid & 31;
    const int wc = w & 1, wm = w >> 1;            // c-half (0..1), m-group (0..7)
    const int bb = blockIdx.y, m0 = blockIdx.x * 128;
    const float* Ab = A + (size_t)bb * NN * NN;
    const float* xT = g_xsT + (size_t)bb * 64 * NN;

    float acc[2][2][4];
#pragma unroll
    for (int mt = 0; mt < 2; mt++)
#pragma unroll
        for (int nt = 0; nt < 2; nt++)
#pragma unroll
            for (int j = 0; j < 4; j++) acc[mt][nt][j] = 0.f;

    // per-thread load coords (512 threads: xsT 1 cp16, A-tile 2 cp16)
    const int la_c = tid >> 3, la_q = tid & 7;
    const int lb_n = tid >> 5, lb_q = tid & 31;   // +512 -> n += 16

    auto issue = [&](int ch) {
        const int k0 = ch * 32;
        uint32_t sa = smb + (ch % NSTAGE) * STAGE_BYTES, sb = sa + SA_BYTES;
        cp16(sa + la_c * (SA_STRIDE * 4) + la_q * 16, xT + (size_t)la_c * NN + k0 + la_q * 4);
#pragma unroll
        for (int l = 0; l < 2; l++)
            cp16(sb + (lb_n + 16 * l) * (SB_STRIDE * 4) + lb_q * 16,
                 Ab + (size_t)(k0 + lb_n + 16 * l) * NN + m0 + lb_q * 4);
        asm volatile("cp.async.commit_group;");
    };

    issue(0);
    issue(1);

    const int ar = lane >> 2, ac = lane & 3;

    for (int ch = 0; ch < 64; ch++) {
        const int s = ch % NSTAGE;
        asm volatile("cp.async.wait_group 1;");
        __syncthreads();

        if (ch + 2 < 64) issue(ch + 2);   // overlaps compute below; targets stage (ch-1)%3

        const float* sA = sm + s * (STAGE_BYTES / 4);
        const float* sB = sA + SA_BYTES / 4;

#pragma unroll
        for (int ks = 0; ks < 4; ks++) {
            const int kc = ks * 8;
            uint32_t a[2][4];
#pragma unroll
            for (int mt = 0; mt < 2; mt++) {
                const float* base = sA + (wc * 32 + mt * 16 + ar) * SA_STRIDE + kc + ac;
                a[mt][0] = __float_as_uint(base[0]);
                a[mt][1] = __float_as_uint(base[8 * SA_STRIDE]);
                a[mt][2] = __float_as_uint(base[4]);
                a[mt][3] = __float_as_uint(base[8 * SA_STRIDE + 4]);
            }
            uint32_t b[2][2];
#pragma unroll
            for (int nt = 0; nt < 2; nt++) {
                const float* base = sB + (kc + ac) * SB_STRIDE + wm * 16 + nt * 8 + ar;
                b[nt][0] = __float_as_uint(base[0]);
                b[nt][1] = __float_as_uint(base[4 * SB_STRIDE]);
            }
#pragma unroll
            for (int mt = 0; mt < 2; mt++)
#pragma unroll
                for (int nt = 0; nt < 2; nt++)
                    asm volatile(
                        "mma.sync.aligned.m16n8k8.row.col.f32.tf32.tf32.f32 "
                        "{%0,%1,%2,%3}, {%4,%5,%6,%7}, {%8,%9}, {%0,%1,%2,%3};"
                        : "+f"(acc[mt][nt][0]), "+f"(acc[mt][nt][1]),
                          "+f"(acc[mt][nt][2]), "+f"(acc[mt][nt][3])
                        : "r"(a[mt][0]), "r"(a[mt][1]), "r"(a[mt][2]), "r"(a[mt][3]),
                          "r"(b[nt][0]), "r"(b[nt][1]));
        }
    }
    __syncthreads();   // all compute done before smem reuse for xg

    // ---- accumulators -> smem xg[m][68 stride] (conflict-free scatter) ----
#pragma unroll
    for (int mt = 0; mt < 2; mt++)
#pragma unroll
        for (int nt = 0; nt < 2; nt++) {
            int cr = wc * 32 + mt * 16 + (lane >> 2);
            int mc = wm * 16 + nt * 8 + 2 * (lane & 3);
            sm[mc * 68 + cr]           = acc[mt][nt][0];
            sm[(mc + 1) * 68 + cr]     = acc[mt][nt][1];
            sm[mc * 68 + cr + 8]       = acc[mt][nt][2];
            sm[(mc + 1) * 68 + cr + 8] = acc[mt][nt][3];
        }
    if (tid < COUTC) { s_sum[tid] = 0.f; s_sq[tid] = 0.f; }
    __syncthreads();

    // ---- epilogue: h = xg @ W^T + bias, BN stats, store h ----
    // 512 threads: tx = o-group of 8 (16), ty = m-group of 4 (32)
    const float4* W4 = reinterpret_cast<const float4*>(Wm);
    const int tx = tid & 15, ty = tid >> 4;
#pragma unroll
    for (int op = 0; op < 4; op++) {
        int o0 = tx * 8 + op * 2;
        float h0[4], h1[4];
#pragma unroll
        for (int mi = 0; mi < 4; mi++) { h0[mi] = 0.f; h1[mi] = 0.f; }
#pragma unroll
        for (int c4 = 0; c4 < 16; c4++) {
            float4 w0 = W4[(size_t)o0 * 16 + c4];
            float4 w1 = W4[(size_t)(o0 + 1) * 16 + c4];
#pragma unroll
            for (int mi = 0; mi < 4; mi++) {
                float4 g = *reinterpret_cast<const float4*>(&sm[(ty * 4 + mi) * 68 + c4 * 4]);
                h0[mi] += g.x * w0.x + g.y * w0.y + g.z * w0.z + g.w * w0.w;
                h1[mi] += g.x * w1.x + g.y * w1.y + g.z * w1.z + g.w * w1.w;
            }
        }
        float b0 = bias[o0], b1 = bias[o0 + 1];
        float sA2 = 0.f, qA = 0.f, sB2 = 0.f, qB = 0.f;
        size_t base = ((size_t)bb * NN + m0 + ty * 4) * COUTC + o0;
#pragma unroll
        for (int mi = 0; mi < 4; mi++) {
            float v0 = h0[mi] + b0, v1 = h1[mi] + b1;
            sA2 += v0; qA += v0 * v0;
            sB2 += v1; qB += v1 * v1;
            *reinterpret_cast<float2*>(&g_h[base + (size_t)mi * COUTC]) = make_float2(v0, v1);
        }
        atomicAdd(&s_sum[o0], sA2);     atomicAdd(&s_sq[o0], qA);
        atomicAdd(&s_sum[o0 + 1], sB2); atomicAdd(&s_sq[o0 + 1], qB);
    }
    __syncthreads();
    if (tid < COUTC)          atomicAdd(&g_stats[tid], s_sum[tid]);
    else if (tid < 2 * COUTC) atomicAdd(&g_stats[tid], s_sq[tid - COUTC]);
}

// ---------------------------------------------------------------------------
// K3: BN finalize + ReLU (g_h layout == output layout)
// ---------------------------------------------------------------------------
__global__ void k_bn(float* __restrict__ out,
                     const float* __restrict__ gamma,
                     const float* __restrict__ beta) {
    __shared__ float s_scale[COUTC], s_shift[COUTC];
    if (threadIdx.x < COUTC) {
        int o = threadIdx.x;
        float cnt = (float)(BB * NN);
        float mean = g_stats[o] / cnt;
        float var = g_stats[o + COUTC] / cnt - mean * mean;
        float sc = gamma[o] * rsqrtf(var + BN_EPS);
        s_scale[o] = sc;
        s_shift[o] = beta[o] - mean * sc;
    }
    __syncthreads();
    const size_t total = (size_t)BB * NN * COUTC / 4;
    const float4* h4 = reinterpret_cast<const float4*>(g_h);
    float4* o4 = reinterpret_cast<float4*>(out);
    for (size_t idx = (size_t)blockIdx.x * blockDim.x + threadIdx.x; idx < total;
         idx += (size_t)gridDim.x * blockDim.x) {
        float4 v = h4[idx];
        int o = ((int)idx & 31) * 4;
        v.x = fmaxf(fmaf(v.x, s_scale[o + 0], s_shift[o + 0]), 0.f);
        v.y = fmaxf(fmaf(v.y, s_scale[o + 1], s_shift[o + 1]), 0.f);
        v.z = fmaxf(fmaf(v.z, s_scale[o + 2], s_shift[o + 2]), 0.f);
        v.w = fmaxf(fmaf(v.w, s_scale[o + 3], s_shift[o + 3]), 0.f);
        o4[idx] = v;
    }
}

extern "C" void kernel_launch(void* const* d_in, const int* in_sizes, int n_in,
                              void* d_out, int out_size) {
    const float* x     = (const float*)d_in[0];
    const float* A     = (const float*)d_in[1];
    const float* W     = (const float*)d_in[2];
    const float* bias  = (const float*)d_in[3];
    const float* gamma = (const float*)d_in[4];
    const float* beta  = (const float*)d_in[5];
    float* out = (float*)d_out;

    cudaFuncSetAttribute(k_gemm, cudaFuncAttributeMaxDynamicSharedMemorySize, SMEM_BYTES);

    k_rowsum<<<BB * NN / 8, 256>>>(A);
    dim3 gp(NN / 64, BB);
    k_prep<<<gp, 256>>>(x);
    dim3 g2(NN / 128, BB);
    k_gemm<<<g2, 512, SMEM_BYTES>>>(A, W, bias);
    k_bn<<<4096, 256>>>(out, gamma, beta);
}

// round 9
// speedup vs baseline: 1.3876x; 1.3876x over previous
#include <cuda_runtime.h>
#include <cuda_fp16.h>
#include <cstdint>

#define BB 32
#define NN 2048
#define CIN 64
#define COUTC 128
#define ADJ_EPS 1e-6f
#define BN_EPS 1e-5f

// smem geometry (uint32 words; fp16 packed half2)
#define XH_STRIDE 20                      // xh row stride words; conflict-free a-frags
#define XH_BYTES (64 * XH_STRIDE * 4)     // 5120 per stage, 3 stages
#define AH_STRIDE 136                     // Ah row stride words; conflict-free b-frags
#define AH_BYTES (16 * AH_STRIDE * 4)     // 8704 per buffer, 2 buffers
#define AH_BASE (3 * XH_BYTES)            // 15360
#define SMEM_BYTES 34816                  // epilogue needs 128*68*4

// ---------------- scratch (device globals; no allocations allowed) ----------
__device__ float g_invS[BB * NN];
__device__ uint32_t g_xh[(size_t)BB * 64 * 1024]; // paired half2{xs[c][32ch+j], xs[c][32ch+j+16]}
__device__ float g_h[(size_t)BB * NN * COUTC];    // pre-BN activations [b][m][o]
__device__ float g_stats[2 * COUTC];

__device__ __forceinline__ uint32_t smem_u32(const void* p) {
    uint32_t a;
    asm("{ .reg .u64 t; cvta.to.shared.u64 t, %1; cvt.u32.u64 %0, t; }" : "=r"(a) : "l"(p));
    return a;
}
__device__ __forceinline__ void cp16(uint32_t dst, const void* src) {
    asm volatile("cp.async.cg.shared.global [%0], [%1], 16;" :: "r"(dst), "l"(src));
}
__device__ __forceinline__ uint32_t pack2(float lo, float hi) {
    __half2 h = __floats2half2_rn(lo, hi);
    return *reinterpret_cast<uint32_t*>(&h);
}

// ---------------------------------------------------------------------------
// K1: row sums of A (one warp per row); block 0 zeroes g_stats.
// ---------------------------------------------------------------------------
__global__ void k_rowsum(const float* __restrict__ A) {
    if (blockIdx.x == 0 && threadIdx.x < 2 * COUTC) g_stats[threadIdx.x] = 0.f;
    int row = blockIdx.x * (blockDim.x >> 5) + (threadIdx.x >> 5);
    int lane = threadIdx.x & 31;
    if (row >= BB * NN) return;
    const float4* Ar = reinterpret_cast<const float4*>(A + (size_t)row * NN);
    float s = 0.f;
#pragma unroll 4
    for (int i = lane; i < NN / 4; i += 32) {
        float4 v = Ar[i];
        s += v.x + v.y + v.z + v.w;
    }
#pragma unroll
    for (int o = 16; o; o >>= 1) s += __shfl_xor_sync(0xFFFFFFFFu, s, o);
    if (lane == 0) g_invS[row] = 1.0f / (s + ADJ_EPS);
}

// ---------------------------------------------------------------------------
// K1b: paired fp16 xsT: g_xh[b][c][ch*16+j] = half2{xs(n=32ch+j), xs(n=32ch+j+16)}
// ---------------------------------------------------------------------------
__global__ void __launch_bounds__(256) k_prep(const float* __restrict__ x) {
    __shared__ float sx[64 * 65];
    __shared__ float sinv[64];
    const int b = blockIdx.y, n0 = blockIdx.x * 64, tid = threadIdx.x;
    if (tid < 64) sinv[tid] = g_invS[b * NN + n0 + tid];
#pragma unroll
    for (int l = 0; l < 4; l++) {
        int i = tid + 256 * l;
        int n = i >> 4, c4 = i & 15;
        float4 v = *reinterpret_cast<const float4*>(x + ((size_t)b * NN + n0 + n) * 64 + c4 * 4);
        sx[n * 65 + c4 * 4 + 0] = v.x;
        sx[n * 65 + c4 * 4 + 1] = v.y;
        sx[n * 65 + c4 * 4 + 2] = v.z;
        sx[n * 65 + c4 * 4 + 3] = v.w;
    }
    __syncthreads();
#pragma unroll
    for (int l = 0; l < 8; l++) {
        int i = tid + 256 * l;
        int c = i >> 5, q = i & 31;
        int half = q >> 4, j = q & 15;
        int nl = half * 32 + j, nh = nl + 16;
        g_xh[(size_t)(b * 64 + c) * 1024 + (n0 / 32 + half) * 16 + j] =
            pack2(sx[nl * 65 + c] * sinv[nl], sx[nh * 65 + c] * sinv[nh]);
    }
}

// ---------------------------------------------------------------------------
// K2: fp16 m16n8k16 mma GEMM with IN-KERNEL fp32->fp16 conversion of A.
// Per CTA: D[c(64), m(128)] = sum_n xh[c][n] * A[n][m0+m]*invS[n], K = 2048.
// A strip is CTA-exclusive: LDG.128 fp32 -> pack (k,k+16) half2 -> STS.128.
// xh via 3-stage cp.async ring; Ah reg-double-buffered (2 smem buffers).
// ---------------------------------------------------------------------------
__global__ void __launch_bounds__(256, 2) k_gemm(const float* __restrict__ A,
                                                 const float* __restrict__ Wm,
                                                 const float* __restrict__ bias) {
    extern __shared__ float sm[];
    __shared__ float s_sum[COUTC], s_sq[COUTC];

    char* smc = reinterpret_cast<char*>(sm);
    const uint32_t smb = smem_u32(sm);
    const int tid = threadIdx.x;
    const int w = tid >> 5, lane = tid & 31;
    const int bb = blockIdx.y, m0 = blockIdx.x * 128;
    const float* Ab = A + (size_t)bb * NN * NN;
    const uint32_t* xhb = g_xh + (size_t)bb * 64 * 1024;

    float acc[4][2][4];
#pragma unroll
    for (int mt = 0; mt < 4; mt++)
#pragma unroll
        for (int nt = 0; nt < 2; nt++)
#pragma unroll
            for (int j = 0; j < 4; j++) acc[mt][nt][j] = 0.f;

    // xh cp.async coords: c = tid>>2 (64 rows), q = tid&3 (4x16B per 64B row)
    const int lx_c = tid >> 2, lx_q = tid & 3;

    // A ldg: rows (k0+w, +16) and (k0+w+8, +24), m-quad = lane
    float4 abuf[4];
    const float* Abase = Ab + (size_t)(m0 + lane * 4) + (size_t)w * NN;

#define ISSUE_XH(ch)                                                          \
    cp16(smb + ((ch) % 3) * XH_BYTES + lx_c * (XH_STRIDE * 4) + lx_q * 16,    \
         xhb + (size_t)lx_c * 1024 + (ch) * 16 + lx_q * 4)

#define LDG_A(ch) do {                                                        \
    const float* p = Abase + (size_t)(ch) * 32 * NN;                          \
    abuf[0] = *reinterpret_cast<const float4*>(p);                            \
    abuf[1] = *reinterpret_cast<const float4*>(p + 16 * NN);                  \
    abuf[2] = *reinterpret_cast<const float4*>(p + 8 * NN);                   \
    abuf[3] = *reinterpret_cast<const float4*>(p + 24 * NN);                  \
} while (0)

#define STS_A(ch) do {                                                        \
    char* sb = smc + AH_BASE + ((ch) & 1) * AH_BYTES;                         \
    uint4 p0, p1;                                                             \
    p0.x = pack2(abuf[0].x, abuf[1].x); p0.y = pack2(abuf[0].y, abuf[1].y);   \
    p0.z = pack2(abuf[0].z, abuf[1].z); p0.w = pack2(abuf[0].w, abuf[1].w);   \
    p1.x = pack2(abuf[2].x, abuf[3].x); p1.y = pack2(abuf[2].y, abuf[3].y);   \
    p1.z = pack2(abuf[2].z, abuf[3].z); p1.w = pack2(abuf[2].w, abuf[3].w);   \
    *reinterpret_cast<uint4*>(sb + w * (AH_STRIDE * 4) + lane * 16) = p0;     \
    *reinterpret_cast<uint4*>(sb + (w + 8) * (AH_STRIDE * 4) + lane * 16) = p1; \
} while (0)

    ISSUE_XH(0);
    asm volatile("cp.async.commit_group;");
    ISSUE_XH(1);
    asm volatile("cp.async.commit_group;");
    LDG_A(0);

    const int ar = lane >> 2, ac = lane & 3;

    for (int ch = 0; ch < 64; ch++) {
        STS_A(ch);
        asm volatile("cp.async.wait_group 1;");
        __syncthreads();

        if (ch + 1 < 64) LDG_A(ch + 1);          // latency overlaps compute
        if (ch + 2 < 64) ISSUE_XH(ch + 2);       // targets stage (ch-1)%3, all readers done
        asm volatile("cp.async.commit_group;");

        const uint32_t* sA = reinterpret_cast<const uint32_t*>(smc + (ch % 3) * XH_BYTES);
        const uint32_t* sB = reinterpret_cast<const uint32_t*>(smc + AH_BASE + (ch & 1) * AH_BYTES);

#pragma unroll
        for (int ks = 0; ks < 2; ks++) {
            uint32_t a[4][4];
#pragma unroll
            for (int mt = 0; mt < 4; mt++) {
                const uint32_t* b0 = sA + (mt * 16 + ar) * XH_STRIDE + ks * 8 + ac;
                const uint32_t* b1 = sA + (mt * 16 + ar + 8) * XH_STRIDE + ks * 8 + ac;
                a[mt][0] = b0[0];
                a[mt][1] = b1[0];
                a[mt][2] = b0[4];
                a[mt][3] = b1[4];
            }
            uint32_t b[2][2];
#pragma unroll
            for (int nt = 0; nt < 2; nt++) {
                const uint32_t* base = sB + (ks * 8 + ac) * AH_STRIDE + w * 16 + nt * 8 + ar;
                b[nt][0] = base[0];
                b[nt][1] = base[4 * AH_STRIDE];
            }
#pragma unroll
            for (int mt = 0; mt < 4; mt++)
#pragma unroll
                for (int nt = 0; nt < 2; nt++)
                    asm volatile(
                        "mma.sync.aligned.m16n8k16.row.col.f32.f16.f16.f32 "
                        "{%0,%1,%2,%3}, {%4,%5,%6,%7}, {%8,%9}, {%0,%1,%2,%3};"
                        : "+f"(acc[mt][nt][0]), "+f"(acc[mt][nt][1]),
                          "+f"(acc[mt][nt][2]), "+f"(acc[mt][nt][3])
                        : "r"(a[mt][0]), "r"(a[mt][1]), "r"(a[mt][2]), "r"(a[mt][3]),
                          "r"(b[nt][0]), "r"(b[nt][1]));
        }
    }
    __syncthreads();   // all compute done before smem reuse for xg

    // ---- accumulators -> smem xg[m][68 stride] (conflict-free scatter) ----
#pragma unroll
    for (int mt = 0; mt < 4; mt++)
#pragma unroll
        for (int nt = 0; nt < 2; nt++) {
            int cr = mt * 16 + (lane >> 2);
            int mc = w * 16 + nt * 8 + 2 * (lane & 3);
            sm[mc * 68 + cr]           = acc[mt][nt][0];
            sm[(mc + 1) * 68 + cr]     = acc[mt][nt][1];
            sm[mc * 68 + cr + 8]       = acc[mt][nt][2];
            sm[(mc + 1) * 68 + cr + 8] = acc[mt][nt][3];
        }
    if (tid < COUTC) { s_sum[tid] = 0.f; s_sq[tid] = 0.f; }
    __syncthreads();

    // ---- epilogue: h = xg @ W^T + bias, BN stats, store h ----
    const float4* W4 = reinterpret_cast<const float4*>(Wm);
    const int tx = tid & 15, ty = tid >> 4;
#pragma unroll
    for (int op = 0; op < 4; op++) {
        int o0 = tx * 8 + op * 2;
        float h0[8], h1[8];
#pragma unroll
        for (int mi = 0; mi < 8; mi++) { h0[mi] = 0.f; h1[mi] = 0.f; }
#pragma unroll
        for (int c4 = 0; c4 < 16; c4++) {
            float4 w0 = W4[(size_t)o0 * 16 + c4];
            float4 w1 = W4[(size_t)(o0 + 1) * 16 + c4];
#pragma unroll
            for (int mi = 0; mi < 8; mi++) {
                float4 g = *reinterpret_cast<const float4*>(&sm[(ty * 8 + mi) * 68 + c4 * 4]);
                h0[mi] += g.x * w0.x + g.y * w0.y + g.z * w0.z + g.w * w0.w;
                h1[mi] += g.x * w1.x + g.y * w1.y + g.z * w1.z + g.w * w1.w;
            }
        }
        float b0 = bias[o0], b1 = bias[o0 + 1];
        float sA2 = 0.f, qA = 0.f, sB2 = 0.f, qB = 0.f;
        size_t base = ((size_t)bb * NN + m0 + ty * 8) * COUTC + o0;
#pragma unroll
        for (int mi = 0; mi < 8; mi++) {
            float v0 = h0[mi] + b0, v1 = h1[mi] + b1;
            sA2 += v0; qA += v0 * v0;
            sB2 += v1; qB += v1 * v1;
            *reinterpret_cast<float2*>(&g_h[base + (size_t)mi * COUTC]) = make_float2(v0, v1);
        }
        atomicAdd(&s_sum[o0], sA2);     atomicAdd(&s_sq[o0], qA);
        atomicAdd(&s_sum[o0 + 1], sB2); atomicAdd(&s_sq[o0 + 1], qB);
    }
    __syncthreads();
    if (tid < COUTC)          atomicAdd(&g_stats[tid], s_sum[tid]);
    else if (tid < 2 * COUTC) atomicAdd(&g_stats[tid], s_sq[tid - COUTC]);
}

// ---------------------------------------------------------------------------
// K3: BN finalize + ReLU (g_h layout == output layout)
// ---------------------------------------------------------------------------
__global__ void k_bn(float* __restrict__ out,
                     const float* __restrict__ gamma,
                     const float* __restrict__ beta) {
    __shared__ float s_scale[COUTC], s_shift[COUTC];
    if (threadIdx.x < COUTC) {
        int o = threadIdx.x;
        float cnt = (float)(BB * NN);
        float mean = g_stats[o] / cnt;
        float var = g_stats[o + COUTC] / cnt - mean * mean;
        float sc = gamma[o] * rsqrtf(var + BN_EPS);
        s_scale[o] = sc;
        s_shift[o] = beta[o] - mean * sc;
    }
    __syncthreads();
    const size_t total = (size_t)BB * NN * COUTC / 4;
    const float4* h4 = reinterpret_cast<const float4*>(g_h);
    float4* o4 = reinterpret_cast<float4*>(out);
    for (size_t idx = (size_t)blockIdx.x * blockDim.x + threadIdx.x; idx < total;
         idx += (size_t)gridDim.x * blockDim.x) {
        float4 v = h4[idx];
        int o = ((int)idx & 31) * 4;
        v.x = fmaxf(fmaf(v.x, s_scale[o + 0], s_shift[o + 0]), 0.f);
        v.y = fmaxf(fmaf(v.y, s_scale[o + 1], s_shift[o + 1]), 0.f);
        v.z = fmaxf(fmaf(v.z, s_scale[o + 2], s_shift[o + 2]), 0.f);
        v.w = fmaxf(fmaf(v.w, s_scale[o + 3], s_shift[o + 3]), 0.f);
        o4[idx] = v;
    }
}

extern "C" void kernel_launch(void* const* d_in, const int* in_sizes, int n_in,
                              void* d_out, int out_size) {
    const float* x     = (const float*)d_in[0];
    const float* A     = (const float*)d_in[1];
    const float* W     = (const float*)d_in[2];
    const float* bias  = (const float*)d_in[3];
    const float* gamma = (const float*)d_in[4];
    const float* beta  = (const float*)d_in[5];
    float* out = (float*)d_out;

    cudaFuncSetAttribute(k_gemm, cudaFuncAttributeMaxDynamicSharedMemorySize, SMEM_BYTES);

    k_rowsum<<<BB * NN / 8, 256>>>(A);
    dim3 gp(NN / 64, BB);
    k_prep<<<gp, 256>>>(x);
    dim3 g2(NN / 128, BB);
    k_gemm<<<g2, 256, SMEM_BYTES>>>(A, W, bias);
    k_bn<<<4096, 256>>>(out, gamma, beta);
}

// round 12
// speedup vs baseline: 1.4603x; 1.0524x over previous
#include <cuda_runtime.h>
#include <cuda_fp16.h>
#include <cstdint>

#define BB 32
#define NN 2048
#define CIN 64
#define COUTC 128
#define ADJ_EPS 1e-6f
#define BN_EPS 1e-5f

// smem geometry (uint32 words; fp16 packed half2)
#define XH_STRIDE 36                       // xh row stride words (128B data + pad); (4ar+ac)%32 distinct
#define XH_STAGE (64 * XH_STRIDE * 4)      // 9216 per stage, 3 stages
#define AH_STRIDE 136                      // Ah row stride words; (8ac+ar)%32 distinct
#define AH_BYTES (32 * AH_STRIDE * 4)      // 17408 per buffer, 2 buffers
#define AH_BASE (3 * XH_STAGE)             // 27648
#define SMEM_BYTES (AH_BASE + 2 * AH_BYTES) // 62464 (epilogue needs 34816, fits)

// ---------------- scratch (device globals; no allocations allowed) ----------
__device__ float g_invS[BB * NN];
__device__ uint32_t g_xh[(size_t)BB * 64 * 1024]; // half2{xs[c][32g+j], xs[c][32g+j+16]}
__device__ float g_h[(size_t)BB * NN * COUTC];    // pre-BN activations [b][m][o]
__device__ float g_stats[2 * COUTC];

__device__ __forceinline__ uint32_t smem_u32(const void* p) {
    uint32_t a;
    asm("{ .reg .u64 t; cvta.to.shared.u64 t, %1; cvt.u32.u64 %0, t; }" : "=r"(a) : "l"(p));
    return a;
}
__device__ __forceinline__ void cp16(uint32_t dst, const void* src) {
    asm volatile("cp.async.cg.shared.global [%0], [%1], 16;" :: "r"(dst), "l"(src));
}
__device__ __forceinline__ uint32_t pack2(float lo, float hi) {
    __half2 h = __floats2half2_rn(lo, hi);
    return *reinterpret_cast<uint32_t*>(&h);
}

// ---------------------------------------------------------------------------
// K0: trivial — zero g_stats. Also shifts the ncu capture slot onto k_gemm.
// ---------------------------------------------------------------------------
__global__ void k_zero() {
    if (threadIdx.x < 2 * COUTC) g_stats[threadIdx.x] = 0.f;
}

// ---------------------------------------------------------------------------
// K1: row sums of A (one warp per row).
// ---------------------------------------------------------------------------
__global__ void k_rowsum(const float* __restrict__ A) {
    int row = blockIdx.x * (blockDim.x >> 5) + (threadIdx.x >> 5);
    int lane = threadIdx.x & 31;
    if (row >= BB * NN) return;
    const float4* Ar = reinterpret_cast<const float4*>(A + (size_t)row * NN);
    float s = 0.f;
#pragma unroll 4
    for (int i = lane; i < NN / 4; i += 32) {
        float4 v = Ar[i];
        s += v.x + v.y + v.z + v.w;
    }
#pragma unroll
    for (int o = 16; o; o >>= 1) s += __shfl_xor_sync(0xFFFFFFFFu, s, o);
    if (lane == 0) g_invS[row] = 1.0f / (s + ADJ_EPS);
}

// ---------------------------------------------------------------------------
// K1b: paired fp16 xsT: g_xh[b][c][g*16+j] = half2{xs(32g+j), xs(32g+j+16)}
// ---------------------------------------------------------------------------
__global__ void __launch_bounds__(256) k_prep(const float* __restrict__ x) {
    __shared__ float sx[64 * 65];
    __shared__ float sinv[64];
    const int b = blockIdx.y, n0 = blockIdx.x * 64, tid = threadIdx.x;
    if (tid < 64) sinv[tid] = g_invS[b * NN + n0 + tid];
#pragma unroll
    for (int l = 0; l < 4; l++) {
        int i = tid + 256 * l;
        int n = i >> 4, c4 = i & 15;
        float4 v = *reinterpret_cast<const float4*>(x + ((size_t)b * NN + n0 + n) * 64 + c4 * 4);
        sx[n * 65 + c4 * 4 + 0] = v.x;
        sx[n * 65 + c4 * 4 + 1] = v.y;
        sx[n * 65 + c4 * 4 + 2] = v.z;
        sx[n * 65 + c4 * 4 + 3] = v.w;
    }
    __syncthreads();
#pragma unroll
    for (int l = 0; l < 8; l++) {
        int i = tid + 256 * l;
        int c = i >> 5, q = i & 31;
        int half = q >> 4, j = q & 15;
        int nl = half * 32 + j, nh = nl + 16;
        g_xh[(size_t)(b * 64 + c) * 1024 + (n0 / 32 + half) * 16 + j] =
            pack2(sx[nl * 65 + c] * sinv[nl], sx[nh * 65 + c] * sinv[nh]);
    }
}

// ---------------------------------------------------------------------------
// K2: fp16 m16n8k16 mma GEMM, in-kernel fp32->fp16 A conversion, 64-k chunks.
// Per CTA: D[c(64), m(128)] = sum_n xh[c][n] * A[n][m0+m]*invS[n], K = 2048.
// 32 iterations, 1 sync + 1 wait each. Warps: wc(2, c-half) x wm(4, m-group).
// ---------------------------------------------------------------------------
__global__ void __launch_bounds__(256, 2) k_gemm(const float* __restrict__ A,
                                                 const float* __restrict__ Wm,
                                                 const float* __restrict__ bias) {
    extern __shared__ float sm[];
    __shared__ float s_sum[COUTC], s_sq[COUTC];

    char* smc = reinterpret_cast<char*>(sm);
    const uint32_t smb = smem_u32(sm);
    const int tid = threadIdx.x;
    const int w = tid >> 5, lane = tid & 31;
    const int wc = w & 1, wm = w >> 1;
    const int bb = blockIdx.y, m0 = blockIdx.x * 128;
    const float* Ab = A + (size_t)bb * NN * NN;
    const uint32_t* xhb = g_xh + (size_t)bb * 64 * 1024;

    float acc[2][4][4];
#pragma unroll
    for (int mt = 0; mt < 2; mt++)
#pragma unroll
        for (int nt = 0; nt < 4; nt++)
#pragma unroll
            for (int j = 0; j < 4; j++) acc[mt][nt][j] = 0.f;

    const int lx_c = tid >> 2, lx_q = tid & 3;
    float4 abuf[8];
    const float* Abase = Ab + (size_t)(m0 + lane * 4) + (size_t)w * NN;

#define ISSUE_XH(ch) do {                                                     \
    uint32_t d = smb + ((ch) % 3) * XH_STAGE + lx_c * (XH_STRIDE * 4);        \
    const uint32_t* s = xhb + (size_t)lx_c * 1024 + (ch) * 32;                \
    cp16(d + lx_q * 16, s + lx_q * 4);                                        \
    cp16(d + 64 + lx_q * 16, s + 16 + lx_q * 4);                              \
} while (0)

#define LDG_A(ch) do {                                                        \
    const float* p = Abase + (size_t)(ch) * 64 * NN;                          \
    abuf[0] = *reinterpret_cast<const float4*>(p);                            \
    abuf[1] = *reinterpret_cast<const float4*>(p + 16 * NN);                  \
    abuf[2] = *reinterpret_cast<const float4*>(p + 8 * NN);                   \
    abuf[3] = *reinterpret_cast<const float4*>(p + 24 * NN);                  \
    abuf[4] = *reinterpret_cast<const float4*>(p + 32 * NN);                  \
    abuf[5] = *reinterpret_cast<const float4*>(p + 48 * NN);                  \
    abuf[6] = *reinterpret_cast<const float4*>(p + 40 * NN);                  \
    abuf[7] = *reinterpret_cast<const float4*>(p + 56 * NN);                  \
} while (0)

#define STS_A(ch) do {                                                        \
    char* sb = smc + AH_BASE + ((ch) & 1) * AH_BYTES;                         \
    _Pragma("unroll")                                                         \
    for (int sp = 0; sp < 2; sp++) {                                          \
        uint4 p0, p1;                                                         \
        float4 a0 = abuf[sp * 4 + 0], a1 = abuf[sp * 4 + 1];                  \
        float4 a2 = abuf[sp * 4 + 2], a3 = abuf[sp * 4 + 3];                  \
        p0.x = pack2(a0.x, a1.x); p0.y = pack2(a0.y, a1.y);                   \
        p0.z = pack2(a0.z, a1.z); p0.w = pack2(a0.w, a1.w);                   \
        p1.x = pack2(a2.x, a3.x); p1.y = pack2(a2.y, a3.y);                   \
        p1.z = pack2(a2.z, a3.z); p1.w = pack2(a2.w, a3.w);                   \
        *reinterpret_cast<uint4*>(sb + (sp * 16 + w) * (AH_STRIDE * 4) + lane * 16) = p0;      \
        *reinterpret_cast<uint4*>(sb + (sp * 16 + w + 8) * (AH_STRIDE * 4) + lane * 16) = p1;  \
    }                                                                         \
} while (0)

    ISSUE_XH(0);
    asm volatile("cp.async.commit_group;");
    ISSUE_XH(1);
    asm volatile("cp.async.commit_group;");
    LDG_A(0);

    const int ar = lane >> 2, ac = lane & 3;

    for (int ch = 0; ch < 32; ch++) {
        STS_A(ch);
        asm volatile("cp.async.wait_group 1;");
        __syncthreads();

        if (ch + 2 < 32) ISSUE_XH(ch + 2);    // stage (ch-1)%3: readers passed this sync
        asm volatile("cp.async.commit_group;");
        if (ch + 1 < 32) LDG_A(ch + 1);       // DRAM latency hidden by compute below

        const uint32_t* sA = reinterpret_cast<const uint32_t*>(smc + (ch % 3) * XH_STAGE);
        const uint32_t* sB = reinterpret_cast<const uint32_t*>(smc + AH_BASE + (ch & 1) * AH_BYTES);

#pragma unroll
        for (int p = 0; p < 4; p++) {
            const int koff = (p >> 1) * 16 + (p & 1) * 8;
            uint32_t a[2][4];
#pragma unroll
            for (int mt = 0; mt < 2; mt++) {
                const uint32_t* b0 = sA + (wc * 32 + mt * 16 + ar) * XH_STRIDE + koff + ac;
                const uint32_t* b1 = b0 + 8 * XH_STRIDE;
                a[mt][0] = b0[0];
                a[mt][1] = b1[0];
                a[mt][2] = b0[4];
                a[mt][3] = b1[4];
            }
            uint32_t b[4][2];
#pragma unroll
            for (int nt = 0; nt < 4; nt++) {
                const uint32_t* base = sB + (koff + ac) * AH_STRIDE + wm * 32 + nt * 8 + ar;
                b[nt][0] = base[0];
                b[nt][1] = base[4 * AH_STRIDE];
            }
#pragma unroll
            for (int mt = 0; mt < 2; mt++)
#pragma unroll
                for (int nt = 0; nt < 4; nt++)
                    asm volatile(
                        "mma.sync.aligned.m16n8k16.row.col.f32.f16.f16.f32 "
                        "{%0,%1,%2,%3}, {%4,%5,%6,%7}, {%8,%9}, {%0,%1,%2,%3};"
                        : "+f"(acc[mt][nt][0]), "+f"(acc[mt][nt][1]),
                          "+f"(acc[mt][nt][2]), "+f"(acc[mt][nt][3])
                        : "r"(a[mt][0]), "r"(a[mt][1]), "r"(a[mt][2]), "r"(a[mt][3]),
                          "r"(b[nt][0]), "r"(b[nt][1]));
        }
    }
    __syncthreads();   // all compute done before smem reuse for xg

    // ---- accumulators -> smem xg[m][68 stride] (conflict-free scatter) ----
#pragma unroll
    for (int mt = 0; mt < 2; mt++)
#pragma unroll
        for (int nt = 0; nt < 4; nt++) {
            int cr = wc * 32 + mt * 16 + (lane >> 2);
            int mc = wm * 32 + nt * 8 + 2 * (lane & 3);
            sm[mc * 68 + cr]           = acc[mt][nt][0];
            sm[(mc + 1) * 68 + cr]     = acc[mt][nt][1];
            sm[mc * 68 + cr + 8]       = acc[mt][nt][2];
            sm[(mc + 1) * 68 + cr + 8] = acc[mt][nt][3];
        }
    if (tid < COUTC) { s_sum[tid] = 0.f; s_sq[tid] = 0.f; }
    __syncthreads();

    // ---- epilogue: h = xg @ W^T + bias, BN stats, store h ----
    const float4* W4 = reinterpret_cast<const float4*>(Wm);
    const int tx = tid & 15, ty = tid >> 4;
#pragma unroll
    for (int op = 0; op < 4; op++) {
        int o0 = tx * 8 + op * 2;
        float h0[8], h1[8];
#pragma unroll
        for (int mi = 0; mi < 8; mi++) { h0[mi] = 0.f; h1[mi] = 0.f; }
#pragma unroll
        for (int c4 = 0; c4 < 16; c4++) {
            float4 w0 = W4[(size_t)o0 * 16 + c4];
            float4 w1 = W4[(size_t)(o0 + 1) * 16 + c4];
#pragma unroll
            for (int mi = 0; mi < 8; mi++) {
                float4 g = *reinterpret_cast<const float4*>(&sm[(ty * 8 + mi) * 68 + c4 * 4]);
                h0[mi] += g.x * w0.x + g.y * w0.y + g.z * w0.z + g.w * w0.w;
                h1[mi] += g.x * w1.x + g.y * w1.y + g.z * w1.z + g.w * w1.w;
            }
        }
        float b0 = bias[o0], b1 = bias[o0 + 1];
        float sA2 = 0.f, qA = 0.f, sB2 = 0.f, qB = 0.f;
        size_t base = ((size_t)bb * NN + m0 + ty * 8) * COUTC + o0;
#pragma unroll
        for (int mi = 0; mi < 8; mi++) {
            float v0 = h0[mi] + b0, v1 = h1[mi] + b1;
            sA2 += v0; qA += v0 * v0;
            sB2 += v1; qB += v1 * v1;
            *reinterpret_cast<float2*>(&g_h[base + (size_t)mi * COUTC]) = make_float2(v0, v1);
        }
        atomicAdd(&s_sum[o0], sA2);     atomicAdd(&s_sq[o0], qA);
        atomicAdd(&s_sum[o0 + 1], sB2); atomicAdd(&s_sq[o0 + 1], qB);
    }
    __syncthreads();
    if (tid < COUTC)          atomicAdd(&g_stats[tid], s_sum[tid]);
    else if (tid < 2 * COUTC) atomicAdd(&g_stats[tid], s_sq[tid - COUTC]);
}

// ---------------------------------------------------------------------------
// K3: BN finalize + ReLU (g_h layout == output layout)
// ---------------------------------------------------------------------------
__global__ void k_bn(float* __restrict__ out,
                     const float* __restrict__ gamma,
                     const float* __restrict__ beta) {
    __shared__ float s_scale[COUTC], s_shift[COUTC];
    if (threadIdx.x < COUTC) {
        int o = threadIdx.x;
        float cnt = (float)(BB * NN);
        float mean = g_stats[o] / cnt;
        float var = g_stats[o + COUTC] / cnt - mean * mean;
        float sc = gamma[o] * rsqrtf(var + BN_EPS);
        s_scale[o] = sc;
        s_shift[o] = beta[o] - mean * sc;
    }
    __syncthreads();
    const size_t total = (size_t)BB * NN * COUTC / 4;
    const float4* h4 = reinterpret_cast<const float4*>(g_h);
    float4* o4 = reinterpret_cast<float4*>(out);
    for (size_t idx = (size_t)blockIdx.x * blockDim.x + threadIdx.x; idx < total;
         idx += (size_t)gridDim.x * blockDim.x) {
        float4 v = h4[idx];
        int o = ((int)idx & 31) * 4;
        v.x = fmaxf(fmaf(v.x, s_scale[o + 0], s_shift[o + 0]), 0.f);
        v.y = fmaxf(fmaf(v.y, s_scale[o + 1], s_shift[o + 1]), 0.f);
        v.z = fmaxf(fmaf(v.z, s_scale[o + 2], s_shift[o + 2]), 0.f);
        v.w = fmaxf(fmaf(v.w, s_scale[o + 3], s_shift[o + 3]), 0.f);
        o4[idx] = v;
    }
}

extern "C" void kernel_launch(void* const* d_in, const int* in_sizes, int n_in,
                              void* d_out, int out_size) {
    const float* x     = (const float*)d_in[0];
    const float* A     = (const float*)d_in[1];
    const float* W     = (const float*)d_in[2];
    const float* bias  = (const float*)d_in[3];
    const float* gamma = (const float*)d_in[4];
    const float* beta  = (const float*)d_in[5];
    float* out = (float*)d_out;

    cudaFuncSetAttribute(k_gemm, cudaFuncAttributeMaxDynamicSharedMemorySize, SMEM_BYTES);

    k_zero<<<1, 256>>>();
    k_rowsum<<<BB * NN / 8, 256>>>(A);
    dim3 gp(NN / 64, BB);
    k_prep<<<gp, 256>>>(x);
    dim3 g2(NN / 128, BB);
    k_gemm<<<g2, 256, SMEM_BYTES>>>(A, W, bias);
    k_bn<<<4096, 256>>>(out, gamma, beta);
}